// round 3
// baseline (speedup 1.0000x reference)
#include <cuda_runtime.h>
#include <math.h>

// Fixed problem shape (GCN_ten): N=200000, E=6400000, F=128, H=16, C=40, 8 hidden layers.
#define MAXN 200704
#define MAXE 6500352
#define HDIM 16

// Scratch (static __device__ arrays — no allocation allowed)
__device__ int   d_counts[MAXN];
__device__ int   d_rowoff[MAXN + 1];
__device__ int   d_cursor[MAXN];
__device__ float d_dis[MAXN];
__device__ int   d_csr[MAXE];
__device__ float d_gA[(size_t)MAXN * HDIM];
__device__ float d_gB[(size_t)MAXN * HDIM];
__device__ int   d_is64;

// ---------------------------------------------------------------------------
// Detect whether edge_index is int64 or int32 (JAX x64-disabled emits int32).
// For int64 little-endian data with node ids < 2^31, every odd 32-bit word of
// the first elements is 0. For int32 data those words are random node ids.
__global__ void detect_kernel(const unsigned int* __restrict__ p, int nwords) {
    int flag = 1;
    int lim = min(64, nwords);
    for (int k = 1; k < lim; k += 2)
        if (p[k] != 0u) flag = 0;
    d_is64 = flag;
}

__global__ void zero_counts(int n) {
    int i = blockIdx.x * blockDim.x + threadIdx.x;
    if (i < n) d_counts[i] = 0;
}

__global__ void count_edges(const void* __restrict__ eidx, int E) {
    int i = blockIdx.x * blockDim.x + threadIdx.x;
    if (i >= E) return;
    int d;
    if (d_is64) d = (int)((const long long*)eidx)[(size_t)E + i];
    else        d = ((const int*)eidx)[E + i];
    atomicAdd(&d_counts[d], 1);
}

__global__ void compute_dis(int n) {
    int i = blockIdx.x * blockDim.x + threadIdx.x;
    if (i < n) d_dis[i] = rsqrtf((float)(d_counts[i] + 1)); // +1 self loop
}

// Single-block exclusive scan of d_counts -> d_rowoff (+ cursor copy).
__global__ void scan_kernel(int n) {
    __shared__ int sums[1024];
    int tid = threadIdx.x;
    int chunk = (n + 1023) >> 10;
    int start = min(tid * chunk, n);
    int end   = min(start + chunk, n);
    int s = 0;
    for (int i = start; i < end; i++) s += d_counts[i];
    sums[tid] = s;
    __syncthreads();
    for (int off = 1; off < 1024; off <<= 1) {
        int t = (tid >= off) ? sums[tid - off] : 0;
        __syncthreads();
        sums[tid] += t;
        __syncthreads();
    }
    int run = sums[tid] - s; // exclusive prefix of this thread's chunk
    for (int i = start; i < end; i++) {
        d_rowoff[i] = run;
        d_cursor[i] = run;
        run += d_counts[i];
    }
    if (tid == 1023) d_rowoff[n] = sums[1023];
}

__global__ void scatter_edges(const void* __restrict__ eidx, int E) {
    int i = blockIdx.x * blockDim.x + threadIdx.x;
    if (i >= E) return;
    int s, d;
    if (d_is64) {
        const long long* p = (const long long*)eidx;
        s = (int)p[i];
        d = (int)p[(size_t)E + i];
    } else {
        const int* p = (const int*)eidx;
        s = p[i];
        d = p[E + i];
    }
    int pos = atomicAdd(&d_cursor[d], 1);
    d_csr[pos] = s;
}

// ---------------------------------------------------------------------------
// Layer 1 matmul: g0[v] = dis[v] * (x[v] @ w_in).  16 threads per node.
__global__ void in_proj(const float* __restrict__ x,
                        const float* __restrict__ w, int n, int F) {
    __shared__ float Wsh[128 * HDIM];
    for (int t = threadIdx.x; t < F * HDIM; t += blockDim.x) Wsh[t] = w[t];
    __syncthreads();
    int g = blockIdx.x * blockDim.x + threadIdx.x;
    int v = g >> 4, j = g & 15;
    if (v >= n) return;
    const float4* xr = (const float4*)(x + (size_t)v * F);
    float acc = 0.f;
#pragma unroll 8
    for (int q = 0; q < 32; q++) {
        float4 xv = __ldg(&xr[q]);
        int f4 = q * 4;
        acc = fmaf(xv.x, Wsh[(f4 + 0) * HDIM + j], acc);
        acc = fmaf(xv.y, Wsh[(f4 + 1) * HDIM + j], acc);
        acc = fmaf(xv.z, Wsh[(f4 + 2) * HDIM + j], acc);
        acc = fmaf(xv.w, Wsh[(f4 + 3) * HDIM + j], acc);
    }
    d_gA[(size_t)v * HDIM + j] = acc * d_dis[v];
}

// ---------------------------------------------------------------------------
// Fused layer: agg(g_in) -> *dis -> (@W) -> +b -> relu -> *dis -> g_out.
// Half-warp per node: lane = half*16 + f. W == nullptr means identity
// (used for layer 1, whose matmul already ran in in_proj).
__global__ void agg_layer(const float* __restrict__ W,
                          const float* __restrict__ bias,
                          int sel, int n) {
    __shared__ float Wsh[HDIM * HDIM];
    __shared__ float bsh[HDIM];
    const float* __restrict__ gin  = sel ? d_gB : d_gA;
    float* __restrict__       gout = sel ? d_gA : d_gB;
    int tid = threadIdx.x;
    if (W != nullptr && tid < HDIM * HDIM) Wsh[tid] = W[tid];
    if (tid < HDIM) bsh[tid] = bias[tid];
    __syncthreads();

    int warp = (blockIdx.x * blockDim.x + tid) >> 5;
    int lane = tid & 31;
    int half = lane >> 4;
    int f    = lane & 15;
    int v    = warp * 2 + half;

    float a = 0.f, dv = 0.f;
    if (v < n) {
        dv = d_dis[v];
        int s = d_rowoff[v];
        int e = d_rowoff[v + 1];
        float acc = __ldg(&gin[(size_t)v * HDIM + f]); // self loop
        int i = s;
        for (; i + 4 <= e; i += 4) {
            int u0 = __ldg(&d_csr[i]);
            int u1 = __ldg(&d_csr[i + 1]);
            int u2 = __ldg(&d_csr[i + 2]);
            int u3 = __ldg(&d_csr[i + 3]);
            float x0 = __ldg(&gin[(size_t)u0 * HDIM + f]);
            float x1 = __ldg(&gin[(size_t)u1 * HDIM + f]);
            float x2 = __ldg(&gin[(size_t)u2 * HDIM + f]);
            float x3 = __ldg(&gin[(size_t)u3 * HDIM + f]);
            acc += x0; acc += x1; acc += x2; acc += x3;
        }
        for (; i < e; i++) acc += __ldg(&gin[(size_t)__ldg(&d_csr[i]) * HDIM + f]);
        a = acc * dv;
    }

    float h;
    if (W != nullptr) {
        h = 0.f;
        int base = half << 4;
#pragma unroll
        for (int k = 0; k < HDIM; k++) {
            float ak = __shfl_sync(0xffffffffu, a, base + k);
            h = fmaf(ak, Wsh[k * HDIM + f], h);
        }
    } else {
        h = a;
    }

    if (v < n) {
        h = fmaxf(h + bsh[f], 0.f);
        gout[(size_t)v * HDIM + f] = h * dv;
    }
}

// ---------------------------------------------------------------------------
// Final layer: agg -> *dis -> @w_out(16xC) + b_out -> log_softmax -> out.
__global__ void final_layer(const float* __restrict__ W,
                            const float* __restrict__ bias,
                            int sel, int n, int C,
                            float* __restrict__ out) {
    __shared__ float Wsh[HDIM * 48];
    __shared__ float bsh[48];
    const float* __restrict__ gin = sel ? d_gB : d_gA;
    int tid = threadIdx.x;
    for (int t = tid; t < HDIM * C; t += blockDim.x) Wsh[t] = W[t];
    for (int t = tid; t < C; t += blockDim.x) bsh[t] = bias[t];
    __syncthreads();

    int warp = (blockIdx.x * blockDim.x + tid) >> 5;
    int lane = tid & 31;
    int half = lane >> 4;
    int f    = lane & 15;
    int v    = warp * 2 + half;

    float a = 0.f;
    if (v < n) {
        float dv = d_dis[v];
        int s = d_rowoff[v];
        int e = d_rowoff[v + 1];
        float acc = __ldg(&gin[(size_t)v * HDIM + f]);
        int i = s;
        for (; i + 4 <= e; i += 4) {
            int u0 = __ldg(&d_csr[i]);
            int u1 = __ldg(&d_csr[i + 1]);
            int u2 = __ldg(&d_csr[i + 2]);
            int u3 = __ldg(&d_csr[i + 3]);
            float x0 = __ldg(&gin[(size_t)u0 * HDIM + f]);
            float x1 = __ldg(&gin[(size_t)u1 * HDIM + f]);
            float x2 = __ldg(&gin[(size_t)u2 * HDIM + f]);
            float x3 = __ldg(&gin[(size_t)u3 * HDIM + f]);
            acc += x0; acc += x1; acc += x2; acc += x3;
        }
        for (; i < e; i++) acc += __ldg(&gin[(size_t)__ldg(&d_csr[i]) * HDIM + f]);
        a = acc * dv;
    }

    int base = half << 4;
    int j0 = f, j1 = f + 16, j2 = f + 32;
    float z0 = bsh[j0];
    float z1 = (j1 < C) ? bsh[j1] : -INFINITY;
    float z2 = (j2 < C) ? bsh[j2] : -INFINITY;
#pragma unroll
    for (int k = 0; k < HDIM; k++) {
        float ak = __shfl_sync(0xffffffffu, a, base + k);
        z0 = fmaf(ak, Wsh[k * C + j0], z0);
        if (j1 < C) z1 = fmaf(ak, Wsh[k * C + j1], z1);
        if (j2 < C) z2 = fmaf(ak, Wsh[k * C + j2], z2);
    }

    // log_softmax over the C values spread across this half-warp (3 regs/lane)
    float m = fmaxf(z0, fmaxf(z1, z2));
#pragma unroll
    for (int o = 8; o; o >>= 1) m = fmaxf(m, __shfl_xor_sync(0xffffffffu, m, o, 16));
    float ssum = expf(z0 - m) + expf(z1 - m) + expf(z2 - m); // exp(-inf)=0
#pragma unroll
    for (int o = 8; o; o >>= 1) ssum += __shfl_xor_sync(0xffffffffu, ssum, o, 16);
    float l = m + logf(ssum);

    if (v < n) {
        size_t rb = (size_t)v * C;
        out[rb + j0] = z0 - l;
        if (j1 < C) out[rb + j1] = z1 - l;
        if (j2 < C) out[rb + j2] = z2 - l;
    }
}

// ---------------------------------------------------------------------------
extern "C" void kernel_launch(void* const* d_in, const int* in_sizes, int n_in,
                              void* d_out, int out_size) {
    const float* x     = (const float*)d_in[0];
    const float* w_in  = (const float*)d_in[1];
    const float* b_in  = (const float*)d_in[2];
    const float* w_hid = (const float*)d_in[3];
    const float* b_hid = (const float*)d_in[4];
    const float* w_out = (const float*)d_in[5];
    const float* b_out = (const float*)d_in[6];
    const void*  eidx  = d_in[7];
    float* out = (float*)d_out;

    const int H = in_sizes[2];           // 16
    const int F = in_sizes[1] / H;       // 128
    const int N = in_sizes[0] / F;       // 200000
    const int C = in_sizes[6];           // 40
    const int L = in_sizes[4] / H;       // 8 hidden layers
    const int E = in_sizes[7] / 2;       // 6400000

    const int TB = 256;
    detect_kernel<<<1, 1>>>((const unsigned int*)eidx, E * 2); // >=2E words if int32
    zero_counts<<<(N + TB - 1) / TB, TB>>>(N);
    count_edges<<<(E + TB - 1) / TB, TB>>>(eidx, E);
    compute_dis<<<(N + TB - 1) / TB, TB>>>(N);
    scan_kernel<<<1, 1024>>>(N);
    scatter_edges<<<(E + TB - 1) / TB, TB>>>(eidx, E);

    in_proj<<<((N * 16) + TB - 1) / TB, TB>>>(x, w_in, N, F);

    int warps = (N + 1) / 2;
    int aggBlocks = (warps * 32 + TB - 1) / TB;

    // layer 1: identity-W (matmul already applied by in_proj), bias b_in
    agg_layer<<<aggBlocks, TB>>>(nullptr, b_in, /*sel=*/0, N);
    int sel = 1;
    for (int i = 0; i < L; i++) {
        agg_layer<<<aggBlocks, TB>>>(w_hid + (size_t)i * H * H,
                                     b_hid + (size_t)i * H, sel, N);
        sel ^= 1;
    }
    final_layer<<<aggBlocks, TB>>>(w_out, b_out, sel, N, C, out);
}